// round 11
// baseline (speedup 1.0000x reference)
#include <cuda_runtime.h>
#include <cuda_fp16.h>
#include <stdint.h>
#include <math.h>

#define N_TOK   4096
#define DM      1024
#define N_EXP   8
#define FFH     2048
#define ROWS_PAD 8832            // aoff[8] max ~8696 + 128 tile overread margin

#define KCH  64                  // halves per K chunk (128 bytes/row)
#define TB   16384               // one 128-row tile: 128*128 bytes
#define STG  (2*TB)              // A+B per stage
#define NSTG 3
#define GSMEM (NSTG*STG)         // 98304 bytes dynamic smem

#define RB   512                 // router blocks in prep kernel
#define CB   1024                // cvt blocks (512 w1 + 512 w2)
#define ZB   128                 // zero-out blocks
#define PREP_GRID (RB + CB + ZB)

// ---------------- device scratch ----------------
__device__ __half g_hbuf[(size_t)ROWS_PAD * FFH];
__device__ __half g_ax[(size_t)ROWS_PAD * DM];
__device__ __half g_w1h[(size_t)N_EXP * FFH * DM];
__device__ __half g_w2h[(size_t)N_EXP * DM * FFH];
__device__ int   g_slot[ROWS_PAD];
__device__ float g_slotw[ROWS_PAD];
__device__ int   g_counts[N_EXP];
__device__ float g_probsum[N_EXP];
__device__ int   g_aoff[N_EXP + 1];
__device__ int   g_cursor[N_EXP];
__device__ int   g_tok_e[N_TOK * 2];
__device__ float g_tok_w[N_TOK * 2];
__device__ int   g_t1off[N_EXP + 1];   // tile prefix for phase 1
__device__ int   g_t2off[N_EXP + 1];   // tile prefix for phase 2
__device__ int   g_ctr1, g_ctr2, g_done;

// ---------------- tiny init ----------------
__global__ void init_small() {
    if (threadIdx.x < N_EXP) {
        g_counts[threadIdx.x]  = 0;
        g_probsum[threadIdx.x] = 0.0f;
    }
    if (threadIdx.x == 0) { g_ctr1 = 0; g_ctr2 = 0; g_done = 0; }
}

// ---------------- fused prep: router || weight cvt || zero out ----------------
__global__ void __launch_bounds__(256) prep_kernel(const float* __restrict__ x,
                                                   const float* __restrict__ rw,
                                                   const float* __restrict__ w1,
                                                   const float* __restrict__ w2,
                                                   __half* __restrict__ w1h,
                                                   __half* __restrict__ w2h,
                                                   float* __restrict__ out,
                                                   int out_elems) {
    const int bb  = blockIdx.x;
    const int tid = threadIdx.x;

    if (bb < RB) {
        __shared__ float s_ps[N_EXP];
        __shared__ int   s_cnt[N_EXP];
        const int wid  = tid >> 5, lane = tid & 31;
        const int warp = bb * 8 + wid;

        if (tid < N_EXP) { s_ps[tid] = 0.0f; s_cnt[tid] = 0; }
        __syncthreads();

        const float4* xr = reinterpret_cast<const float4*>(x + (size_t)warp * DM);
        float4 xv[8];
#pragma unroll
        for (int it = 0; it < 8; it++) xv[it] = xr[lane + it * 32];

        float acc[N_EXP];
#pragma unroll
        for (int e = 0; e < N_EXP; e++) acc[e] = 0.0f;
#pragma unroll
        for (int it = 0; it < 8; it++) {
            const int v4 = lane + it * 32;
#pragma unroll
            for (int e = 0; e < N_EXP; e++) {
                float4 wv = *reinterpret_cast<const float4*>(rw + e * DM + v4 * 4);
                acc[e] += fmaf(xv[it].x, wv.x, fmaf(xv[it].y, wv.y,
                               fmaf(xv[it].z, wv.z, xv[it].w * wv.w)));
            }
        }
#pragma unroll
        for (int e = 0; e < N_EXP; e++) {
#pragma unroll
            for (int o = 16; o > 0; o >>= 1)
                acc[e] += __shfl_xor_sync(0xFFFFFFFFu, acc[e], o);
        }

        if (lane == 0) {
            float m = acc[0];
#pragma unroll
            for (int e = 1; e < N_EXP; e++) m = fmaxf(m, acc[e]);
            float ex[N_EXP], s = 0.0f;
#pragma unroll
            for (int e = 0; e < N_EXP; e++) { ex[e] = expf(acc[e] - m); s += ex[e]; }
            float inv = 1.0f / s;

            int i0 = 0;
#pragma unroll
            for (int e = 1; e < N_EXP; e++) if (acc[e] > acc[i0]) i0 = e;
            int i1 = -1;
#pragma unroll
            for (int e = 0; e < N_EXP; e++) {
                if (e == i0) continue;
                if (i1 < 0 || acc[e] > acc[i1]) i1 = e;
            }
            float p0 = ex[i0] * inv, p1 = ex[i1] * inv;
            float rcp = 1.0f / (p0 + p1);
            g_tok_e[2 * warp + 0] = i0; g_tok_w[2 * warp + 0] = p0 * rcp;
            g_tok_e[2 * warp + 1] = i1; g_tok_w[2 * warp + 1] = p1 * rcp;

            atomicAdd(&s_cnt[i0], 1);
            atomicAdd(&s_cnt[i1], 1);
#pragma unroll
            for (int e = 0; e < N_EXP; e++)
                atomicAdd(&s_ps[e], ex[e] * inv);
        }
        __syncthreads();
        if (tid < N_EXP) {
            atomicAdd(&g_counts[tid],  s_cnt[tid]);
            atomicAdd(&g_probsum[tid], s_ps[tid]);
        }
    } else if (bb < RB + CB) {
        int cb = bb - RB;
        const float* src;
        __half* dst;
        if (cb < CB / 2) { src = w1; dst = w1h; }
        else             { src = w2; dst = w2h; cb -= CB / 2; }
        const int n = N_EXP * FFH * DM;
        const int stride = (CB / 2) * 256 * 4;
        for (int j = (cb * 256 + tid) * 4; j < n; j += stride) {
            float4 v = *reinterpret_cast<const float4*>(src + j);
            *reinterpret_cast<__half2*>(dst + j)     = __float22half2_rn(make_float2(v.x, v.y));
            *reinterpret_cast<__half2*>(dst + j + 2) = __float22half2_rn(make_float2(v.z, v.w));
        }
    } else {
        const int zb = bb - RB - CB;
        const int stride = ZB * 256 * 4;
        const int n4 = out_elems & ~3;
        for (int j = (zb * 256 + tid) * 4; j < n4; j += stride)
            *reinterpret_cast<float4*>(out + j) = make_float4(0.f, 0.f, 0.f, 0.f);
        if (zb == 0 && tid == 0)
            for (int j = n4; j < out_elems; j++) out[j] = 0.0f;
    }
}

// ---------------- finalize: offsets + aux loss + tile prefix sums ----------------
__global__ void finalize_kernel(float* auxp) {
    if (threadIdx.x == 0 && blockIdx.x == 0) {
        int off = 0, t1 = 0, t2 = 0;
        float s = 0.0f;
        for (int e = 0; e < N_EXP; e++) {
            g_aoff[e] = off;
            g_t1off[e] = t1;
            g_t2off[e] = t2;
            int cnt = g_counts[e];
            off += (cnt + 63) & ~63;
            int nrt = (cnt + 127) >> 7;
            t1 += nrt * (FFH / 128);
            t2 += nrt * (DM / 128);
            g_cursor[e] = 0;
            float f_i = (float)cnt / (float)(N_TOK * 2);
            float P_i = g_probsum[e] / (float)N_TOK;
            s += f_i * P_i;
        }
        g_aoff[N_EXP]  = off;
        g_t1off[N_EXP] = t1;
        g_t2off[N_EXP] = t2;
        if (auxp) *auxp = (float)N_EXP * s;
    }
}

// ---------------- scatter ----------------
__global__ void scatter_kernel() {
    int t = blockIdx.x * blockDim.x + threadIdx.x;
    if (t >= N_TOK) return;
#pragma unroll
    for (int k = 0; k < 2; k++) {
        int e = g_tok_e[2 * t + k];
        int p = atomicAdd(&g_cursor[e], 1);
        int idx = g_aoff[e] + p;
        g_slot[idx]  = t;
        g_slotw[idx] = g_tok_w[2 * t + k];
    }
}

// ---------------- gather x into slot order (fp16) ----------------
__global__ void __launch_bounds__(256) gather_kernel(const float* __restrict__ x) {
    int row = blockIdx.x * 2 + (threadIdx.x >> 7);
    int c   = (threadIdx.x & 127) * 8;
    __half* dst = g_ax + (size_t)row * DM + c;

    int e = 0;
#pragma unroll
    for (int k = 1; k < N_EXP; k++) if (row >= g_aoff[k]) e = k;
    bool valid = (row < g_aoff[N_EXP]) && ((row - g_aoff[e]) < g_counts[e]);

    if (valid) {
        const float* s = x + (size_t)g_slot[row] * DM + c;
        float4 v0 = *reinterpret_cast<const float4*>(s);
        float4 v1 = *reinterpret_cast<const float4*>(s + 4);
        *reinterpret_cast<__half2*>(dst)     = __float22half2_rn(make_float2(v0.x, v0.y));
        *reinterpret_cast<__half2*>(dst + 2) = __float22half2_rn(make_float2(v0.z, v0.w));
        *reinterpret_cast<__half2*>(dst + 4) = __float22half2_rn(make_float2(v1.x, v1.y));
        *reinterpret_cast<__half2*>(dst + 6) = __float22half2_rn(make_float2(v1.z, v1.w));
    } else {
        *reinterpret_cast<uint4*>(dst) = make_uint4(0, 0, 0, 0);
    }
}

// ---------------- mma helpers ----------------
__device__ __forceinline__ uint32_t s2u(const void* p) {
    uint32_t a;
    asm("{ .reg .u64 t; cvta.to.shared.u64 t, %1; cvt.u32.u64 %0, t; }" : "=r"(a) : "l"(p));
    return a;
}
__device__ __forceinline__ void mma_f16(float* c, const unsigned* a, const unsigned* b) {
    asm volatile("mma.sync.aligned.m16n8k16.row.col.f32.f16.f16.f32 "
                 "{%0,%1,%2,%3}, {%4,%5,%6,%7}, {%8,%9}, {%0,%1,%2,%3};"
                 : "+f"(c[0]), "+f"(c[1]), "+f"(c[2]), "+f"(c[3])
                 : "r"(a[0]), "r"(a[1]), "r"(a[2]), "r"(a[3]),
                   "r"(b[0]), "r"(b[1]));
}
__device__ __forceinline__ void ldsm_x4(unsigned& r0, unsigned& r1, unsigned& r2, unsigned& r3,
                                        uint32_t addr) {
    asm volatile("ldmatrix.sync.aligned.m8n8.x4.shared.b16 {%0,%1,%2,%3}, [%4];"
                 : "=r"(r0), "=r"(r1), "=r"(r2), "=r"(r3) : "r"(addr));
}
__device__ __forceinline__ void cpa16(uint32_t saddr, const void* gptr) {
    asm volatile("cp.async.cg.shared.global [%0], [%1], 16;" :: "r"(saddr), "l"(gptr));
}
#define CPA_COMMIT() asm volatile("cp.async.commit_group;" ::: "memory")
__device__ __forceinline__ uint32_t swz(uint32_t off) { return off ^ ((off >> 3) & 0x70); }

// =====================================================================
// Pipelined fp16 GEMM core
// =====================================================================
struct GemmCtx {
    uint32_t smu;
    uint32_t sa_off[4];
    uint32_t ga_off[4];
    int wm, wn, a_r, a_k16, b_r, b_k16, g, c2;
};

__device__ __forceinline__ void gemm_setup(GemmCtx& cx, char* sm, int ldk) {
    const int tid = threadIdx.x, wid = tid >> 5, lane = tid & 31;
    cx.smu = s2u(sm);
    cx.wm = wid >> 1; cx.wn = wid & 1;
    cx.a_r = lane & 15;          cx.a_k16 = (lane >> 4) * 16;
    cx.b_r = ((lane >> 4) << 3) + (lane & 7);
    cx.b_k16 = ((lane >> 3) & 1) * 16;
    cx.g = lane >> 2; cx.c2 = (lane & 3) << 1;
#pragma unroll
    for (int t = 0; t < 4; t++) {
        int idx = tid + t * 256;
        int row = idx >> 3, c16 = idx & 7;
        cx.sa_off[t] = swz((uint32_t)(row * 128 + c16 * 16));
        cx.ga_off[t] = (uint32_t)(row * ldk + c16 * 8);
    }
}

__device__ __forceinline__ void gemm_load(const GemmCtx& cx, int s,
                                          const __half* ag, const __half* bg, int ks) {
#pragma unroll
    for (int t = 0; t < 4; t++)
        cpa16(cx.smu + s * STG + cx.sa_off[t], ag + cx.ga_off[t] + ks);
#pragma unroll
    for (int t = 0; t < 4; t++)
        cpa16(cx.smu + s * STG + TB + cx.sa_off[t], bg + cx.ga_off[t] + ks);
    CPA_COMMIT();
}

__device__ __forceinline__ void gemm_compute(const GemmCtx& cx, int s, float acc[2][8][4]) {
    const uint32_t sbase = cx.smu + s * STG;
#pragma unroll
    for (int kt = 0; kt < 4; kt++) {
        unsigned a[2][4], b[8][2];
#pragma unroll
        for (int mt = 0; mt < 2; mt++) {
            uint32_t off = (uint32_t)((cx.wm * 32 + mt * 16 + cx.a_r) * 128 + kt * 32 + cx.a_k16);
            ldsm_x4(a[mt][0], a[mt][1], a[mt][2], a[mt][3], sbase + swz(off));
        }
#pragma unroll
        for (int np = 0; np < 4; np++) {
            uint32_t off = (uint32_t)((cx.wn * 64 + np * 16 + cx.b_r) * 128 + kt * 32 + cx.b_k16);
            unsigned r0, r1, r2, r3;
            ldsm_x4(r0, r1, r2, r3, sbase + TB + swz(off));
            b[np * 2][0] = r0; b[np * 2][1] = r1;
            b[np * 2 + 1][0] = r2; b[np * 2 + 1][1] = r3;
        }
#pragma unroll
        for (int mt = 0; mt < 2; mt++)
#pragma unroll
            for (int nt = 0; nt < 8; nt++)
                mma_f16(acc[mt][nt], a[mt], b[nt]);
    }
}

#define GEMM_MAINLOOP(NIT, AG, BG)                                          \
    gemm_load(cx, 0, AG, BG, 0);                                            \
    gemm_load(cx, 1, AG, BG, KCH);                                          \
    for (int it = 0; it < (NIT); it++) {                                    \
        if (it + 2 < (NIT)) asm volatile("cp.async.wait_group 1;" ::: "memory"); \
        else                asm volatile("cp.async.wait_group 0;" ::: "memory"); \
        __syncthreads();                                                    \
        if (it + 2 < (NIT)) gemm_load(cx, (it + 2) % 3, AG, BG, (it + 2) * KCH); \
        gemm_compute(cx, it % 3, acc);                                      \
    }

// =====================================================================
// Persistent fused GEMM: phase1 (x@w1+silu) -> device barrier -> phase2
// Work-stealing over compact tile lists removes wave quantization.
// =====================================================================
__global__ void __launch_bounds__(256, 2) moe_gemm_kernel(const float* __restrict__ b1,
                                                          const float* __restrict__ b2,
                                                          float* __restrict__ out) {
    extern __shared__ __align__(1024) char sm[];
    __shared__ int s_idx;
    const int tid = threadIdx.x;
    GemmCtx cx;

    // ---------------- phase 1 ----------------
    gemm_setup(cx, sm, DM);
    const int total1 = g_t1off[N_EXP];
    while (true) {
        if (tid == 0) s_idx = atomicAdd(&g_ctr1, 1);
        __syncthreads();
        const int idx = s_idx;
        if (idx >= total1) break;

        int e = 0;
#pragma unroll
        for (int k = 0; k < N_EXP - 1; k++) if (idx >= g_t1off[k + 1]) e = k + 1;
        const int local = idx - g_t1off[e];
        const int rt = local >> 4, ct = local & 15;     // FFH/128 = 16 cts
        const int cnt = g_counts[e], base = g_aoff[e];

        const __half* ag = g_ax  + (size_t)(base + rt * 128) * DM;
        const __half* bg = g_w1h + ((size_t)e * FFH + (size_t)ct * 128) * DM;

        float acc[2][8][4];
#pragma unroll
        for (int mt = 0; mt < 2; mt++)
#pragma unroll
            for (int nt = 0; nt < 8; nt++)
#pragma unroll
                for (int q = 0; q < 4; q++) acc[mt][nt][q] = 0.0f;

        GEMM_MAINLOOP(DM / KCH, ag, bg);

#pragma unroll
        for (int mt = 0; mt < 2; mt++) {
#pragma unroll
            for (int hf = 0; hf < 2; hf++) {
                int r = rt * 128 + cx.wm * 32 + mt * 16 + hf * 8 + cx.g;
                if (r >= cnt) continue;
                size_t hrow = (size_t)(base + r) * FFH;
#pragma unroll
                for (int nt = 0; nt < 8; nt++) {
                    int col = ct * 128 + cx.wn * 64 + nt * 8 + cx.c2;
                    float v0 = acc[mt][nt][hf * 2 + 0] + b1[e * FFH + col];
                    float v1 = acc[mt][nt][hf * 2 + 1] + b1[e * FFH + col + 1];
                    float s0 = __fdividef(v0, 1.0f + __expf(-v0));
                    float s1 = __fdividef(v1, 1.0f + __expf(-v1));
                    *reinterpret_cast<__half2*>(&g_hbuf[hrow + col]) =
                        __float22half2_rn(make_float2(s0, s1));
                }
            }
        }
        __syncthreads();
    }

    // ---------------- device-wide barrier ----------------
    __threadfence();
    __syncthreads();
    if (tid == 0) {
        atomicAdd(&g_done, 1);
        while (atomicAdd(&g_done, 0) < (int)gridDim.x) __nanosleep(64);
    }
    __syncthreads();
    __threadfence();

    // ---------------- phase 2 ----------------
    gemm_setup(cx, sm, FFH);
    const int total2 = g_t2off[N_EXP];
    while (true) {
        if (tid == 0) s_idx = atomicAdd(&g_ctr2, 1);
        __syncthreads();
        const int idx = s_idx;
        if (idx >= total2) break;

        int e = 0;
#pragma unroll
        for (int k = 0; k < N_EXP - 1; k++) if (idx >= g_t2off[k + 1]) e = k + 1;
        const int local = idx - g_t2off[e];
        const int rt = local >> 3, ct = local & 7;      // DM/128 = 8 cts
        const int cnt = g_counts[e], base = g_aoff[e];

        const __half* ag = g_hbuf + (size_t)(base + rt * 128) * FFH;
        const __half* bg = g_w2h  + ((size_t)e * DM + (size_t)ct * 128) * FFH;

        float acc[2][8][4];
#pragma unroll
        for (int mt = 0; mt < 2; mt++)
#pragma unroll
            for (int nt = 0; nt < 8; nt++)
#pragma unroll
                for (int q = 0; q < 4; q++) acc[mt][nt][q] = 0.0f;

        GEMM_MAINLOOP(FFH / KCH, ag, bg);

#pragma unroll
        for (int mt = 0; mt < 2; mt++) {
#pragma unroll
            for (int hf = 0; hf < 2; hf++) {
                int r = rt * 128 + cx.wm * 32 + mt * 16 + hf * 8 + cx.g;
                if (r >= cnt) continue;
                int tok  = g_slot[base + r];
                float cw = g_slotw[base + r];
                float* orow = out + (size_t)tok * DM;
#pragma unroll
                for (int nt = 0; nt < 8; nt++) {
                    int col = ct * 128 + cx.wn * 64 + nt * 8 + cx.c2;
                    float v0 = acc[mt][nt][hf * 2 + 0] + b2[e * DM + col];
                    float v1 = acc[mt][nt][hf * 2 + 1] + b2[e * DM + col + 1];
                    atomicAdd(orow + col,     cw * v0);
                    atomicAdd(orow + col + 1, cw * v1);
                }
            }
        }
        __syncthreads();
    }
}

// ---------------- launch ----------------
extern "C" void kernel_launch(void* const* d_in, const int* in_sizes, int n_in,
                              void* d_out, int out_size) {
    const float* x  = (const float*)d_in[0];
    const float* rw = (const float*)d_in[1];
    const float* w1 = (const float*)d_in[2];
    const float* b1 = (const float*)d_in[3];
    const float* w2 = (const float*)d_in[4];
    const float* b2 = (const float*)d_in[5];
    float* out = (float*)d_out;

    float* auxp = (out_size > N_TOK * DM) ? (out + (size_t)N_TOK * DM) : nullptr;

    cudaFuncSetAttribute(moe_gemm_kernel, cudaFuncAttributeMaxDynamicSharedMemorySize, GSMEM);

    // persistent grid = exactly the number of co-resident CTAs (deadlock-free)
    int dev = 0, sms = 0, occ = 0;
    cudaGetDevice(&dev);
    cudaDeviceGetAttribute(&sms, cudaDevAttrMultiProcessorCount, dev);
    cudaOccupancyMaxActiveBlocksPerMultiprocessor(&occ, moe_gemm_kernel, 256, GSMEM);
    if (occ < 1) occ = 1;
    if (occ > 2) occ = 2;
    const int pgrid = sms * occ;

    __half* w1h; cudaGetSymbolAddress((void**)&w1h, g_w1h);
    __half* w2h; cudaGetSymbolAddress((void**)&w2h, g_w2h);

    init_small<<<1, 32>>>();
    prep_kernel<<<PREP_GRID, 256>>>(x, rw, w1, w2, w1h, w2h, out, out_size);
    finalize_kernel<<<1, 32>>>(auxp);
    scatter_kernel<<<(N_TOK + 255) / 256, 256>>>();
    gather_kernel<<<ROWS_PAD / 2, 256>>>(x);

    moe_gemm_kernel<<<pgrid, 256, GSMEM>>>(b1, b2, out);
}

// round 12
// speedup vs baseline: 1.0866x; 1.0866x over previous
#include <cuda_runtime.h>
#include <cuda_fp16.h>
#include <stdint.h>
#include <math.h>

#define N_TOK   4096
#define DM      1024
#define N_EXP   8
#define FFH     2048
#define ROWS_PAD 8704

#define KCH  64                 // halves per K chunk (128 bytes/row)
#define TB   16384              // one 128-row tile: 128*128 bytes
#define STG  (2*TB)             // A+B per stage
#define NSTG 3
#define GSMEM (NSTG*STG)        // 98304 bytes dynamic smem

#define RB   512                // router blocks in prep kernel
#define CB   512                // w1 cvt blocks (w2 cvt rides in gemm1)
#define ZB   128                // zero-out blocks
#define PREP_GRID (RB + CB + ZB)

#define W2_ELEMS (N_EXP * DM * FFH)      // 16.8M
#define W2_STRIPES 4096                  // one per guaranteed-idle gemm1 block
#define W2_SE (W2_ELEMS / W2_STRIPES)    // 4096 elements per stripe

// ---------------- device scratch ----------------
__device__ __half g_hbuf[(size_t)ROWS_PAD * FFH];    // fp16 hidden acts
__device__ __half g_ax[(size_t)ROWS_PAD * DM];       // fp16 gathered x
__device__ __half g_w1h[(size_t)N_EXP * FFH * DM];   // fp16 w1
__device__ __half g_w2h[(size_t)N_EXP * DM * FFH];   // fp16 w2
__device__ int   g_slot[ROWS_PAD];
__device__ float g_slotw[ROWS_PAD];
__device__ int   g_counts[N_EXP];
__device__ float g_probsum[N_EXP];
__device__ int   g_aoff[N_EXP + 1];
__device__ int   g_cursor[N_EXP];
__device__ int   g_tok_e[N_TOK * 2];
__device__ float g_tok_w[N_TOK * 2];

// ---------------- tiny init ----------------
__global__ void init_small() {
    if (threadIdx.x < N_EXP) {
        g_counts[threadIdx.x]  = 0;
        g_probsum[threadIdx.x] = 0.0f;
    }
}

// ---------------- fused prep: router || w1 cvt || zero out ----------------
__global__ void __launch_bounds__(256) prep_kernel(const float* __restrict__ x,
                                                   const float* __restrict__ rw,
                                                   const float* __restrict__ w1,
                                                   __half* __restrict__ w1h,
                                                   float* __restrict__ out,
                                                   int out_elems) {
    const int bb  = blockIdx.x;
    const int tid = threadIdx.x;

    if (bb < RB) {
        // ---------- router: warp per token, x prefetched (MLP=8) ----------
        __shared__ float s_ps[N_EXP];
        __shared__ int   s_cnt[N_EXP];
        const int wid  = tid >> 5, lane = tid & 31;
        const int warp = bb * 8 + wid;          // token id (RB*8 == N_TOK)

        if (tid < N_EXP) { s_ps[tid] = 0.0f; s_cnt[tid] = 0; }
        __syncthreads();

        const float4* xr = reinterpret_cast<const float4*>(x + (size_t)warp * DM);
        float4 xv[8];
#pragma unroll
        for (int it = 0; it < 8; it++) xv[it] = xr[lane + it * 32];

        float acc[N_EXP];
#pragma unroll
        for (int e = 0; e < N_EXP; e++) acc[e] = 0.0f;
#pragma unroll
        for (int it = 0; it < 8; it++) {
            const int v4 = lane + it * 32;
#pragma unroll
            for (int e = 0; e < N_EXP; e++) {
                float4 wv = *reinterpret_cast<const float4*>(rw + e * DM + v4 * 4);
                acc[e] += fmaf(xv[it].x, wv.x, fmaf(xv[it].y, wv.y,
                               fmaf(xv[it].z, wv.z, xv[it].w * wv.w)));
            }
        }
#pragma unroll
        for (int e = 0; e < N_EXP; e++) {
#pragma unroll
            for (int o = 16; o > 0; o >>= 1)
                acc[e] += __shfl_xor_sync(0xFFFFFFFFu, acc[e], o);
        }

        if (lane == 0) {
            float m = acc[0];
#pragma unroll
            for (int e = 1; e < N_EXP; e++) m = fmaxf(m, acc[e]);
            float ex[N_EXP], s = 0.0f;
#pragma unroll
            for (int e = 0; e < N_EXP; e++) { ex[e] = expf(acc[e] - m); s += ex[e]; }
            float inv = 1.0f / s;

            int i0 = 0;
#pragma unroll
            for (int e = 1; e < N_EXP; e++) if (acc[e] > acc[i0]) i0 = e;
            int i1 = -1;
#pragma unroll
            for (int e = 0; e < N_EXP; e++) {
                if (e == i0) continue;
                if (i1 < 0 || acc[e] > acc[i1]) i1 = e;
            }
            float p0 = ex[i0] * inv, p1 = ex[i1] * inv;
            float rcp = 1.0f / (p0 + p1);
            g_tok_e[2 * warp + 0] = i0; g_tok_w[2 * warp + 0] = p0 * rcp;
            g_tok_e[2 * warp + 1] = i1; g_tok_w[2 * warp + 1] = p1 * rcp;

            atomicAdd(&s_cnt[i0], 1);
            atomicAdd(&s_cnt[i1], 1);
#pragma unroll
            for (int e = 0; e < N_EXP; e++)
                atomicAdd(&s_ps[e], ex[e] * inv);
        }
        __syncthreads();
        if (tid < N_EXP) {
            atomicAdd(&g_counts[tid],  s_cnt[tid]);
            atomicAdd(&g_probsum[tid], s_ps[tid]);
        }
    } else if (bb < RB + CB) {
        // ---------- w1 fp32 -> fp16 ----------
        const int cb = bb - RB;
        const int n = N_EXP * FFH * DM;
        const int stride = CB * 256 * 4;
        for (int j = (cb * 256 + tid) * 4; j < n; j += stride) {
            float4 v = *reinterpret_cast<const float4*>(w1 + j);
            *reinterpret_cast<__half2*>(w1h + j)     = __float22half2_rn(make_float2(v.x, v.y));
            *reinterpret_cast<__half2*>(w1h + j + 2) = __float22half2_rn(make_float2(v.z, v.w));
        }
    } else {
        // ---------- zero output ----------
        const int zb = bb - RB - CB;
        const int stride = ZB * 256 * 4;
        const int n4 = out_elems & ~3;
        for (int j = (zb * 256 + tid) * 4; j < n4; j += stride)
            *reinterpret_cast<float4*>(out + j) = make_float4(0.f, 0.f, 0.f, 0.f);
        if (zb == 0 && tid == 0)
            for (int j = n4; j < out_elems; j++) out[j] = 0.0f;
    }
}

// ---------------- finalize ----------------
__global__ void finalize_kernel(float* auxp) {
    if (threadIdx.x == 0 && blockIdx.x == 0) {
        int off = 0;
        float s = 0.0f;
        for (int e = 0; e < N_EXP; e++) {
            g_aoff[e] = off;
            off += (g_counts[e] + 63) & ~63;
            g_cursor[e] = 0;
            float f_i = (float)g_counts[e] / (float)(N_TOK * 2);
            float P_i = g_probsum[e] / (float)N_TOK;
            s += f_i * P_i;
        }
        g_aoff[N_EXP] = off;
        if (auxp) *auxp = (float)N_EXP * s;
    }
}

// ---------------- scatter ----------------
__global__ void scatter_kernel() {
    int t = blockIdx.x * blockDim.x + threadIdx.x;
    if (t >= N_TOK) return;
#pragma unroll
    for (int k = 0; k < 2; k++) {
        int e = g_tok_e[2 * t + k];
        int p = atomicAdd(&g_cursor[e], 1);
        int idx = g_aoff[e] + p;
        g_slot[idx]  = t;
        g_slotw[idx] = g_tok_w[2 * t + k];
    }
}

// ---------------- gather x into slot order (fp16) ----------------
__global__ void __launch_bounds__(256) gather_kernel(const float* __restrict__ x) {
    int row = blockIdx.x * 2 + (threadIdx.x >> 7);
    int c   = (threadIdx.x & 127) * 8;
    __half* dst = g_ax + (size_t)row * DM + c;

    int e = 0;
#pragma unroll
    for (int k = 1; k < N_EXP; k++) if (row >= g_aoff[k]) e = k;
    bool valid = (row < g_aoff[N_EXP]) && ((row - g_aoff[e]) < g_counts[e]);

    if (valid) {
        const float* s = x + (size_t)g_slot[row] * DM + c;
        float4 v0 = *reinterpret_cast<const float4*>(s);
        float4 v1 = *reinterpret_cast<const float4*>(s + 4);
        *reinterpret_cast<__half2*>(dst)     = __float22half2_rn(make_float2(v0.x, v0.y));
        *reinterpret_cast<__half2*>(dst + 2) = __float22half2_rn(make_float2(v0.z, v0.w));
        *reinterpret_cast<__half2*>(dst + 4) = __float22half2_rn(make_float2(v1.x, v1.y));
        *reinterpret_cast<__half2*>(dst + 6) = __float22half2_rn(make_float2(v1.z, v1.w));
    } else {
        *reinterpret_cast<uint4*>(dst) = make_uint4(0, 0, 0, 0);
    }
}

// ---------------- mma helpers ----------------
__device__ __forceinline__ uint32_t s2u(const void* p) {
    uint32_t a;
    asm("{ .reg .u64 t; cvta.to.shared.u64 t, %1; cvt.u32.u64 %0, t; }" : "=r"(a) : "l"(p));
    return a;
}
__device__ __forceinline__ void mma_f16(float* c, const unsigned* a, const unsigned* b) {
    asm volatile("mma.sync.aligned.m16n8k16.row.col.f32.f16.f16.f32 "
                 "{%0,%1,%2,%3}, {%4,%5,%6,%7}, {%8,%9}, {%0,%1,%2,%3};"
                 : "+f"(c[0]), "+f"(c[1]), "+f"(c[2]), "+f"(c[3])
                 : "r"(a[0]), "r"(a[1]), "r"(a[2]), "r"(a[3]),
                   "r"(b[0]), "r"(b[1]));
}
__device__ __forceinline__ void ldsm_x4(unsigned& r0, unsigned& r1, unsigned& r2, unsigned& r3,
                                        uint32_t addr) {
    asm volatile("ldmatrix.sync.aligned.m8n8.x4.shared.b16 {%0,%1,%2,%3}, [%4];"
                 : "=r"(r0), "=r"(r1), "=r"(r2), "=r"(r3) : "r"(addr));
}
__device__ __forceinline__ void cpa16(uint32_t saddr, const void* gptr) {
    asm volatile("cp.async.cg.shared.global [%0], [%1], 16;" :: "r"(saddr), "l"(gptr));
}
#define CPA_COMMIT() asm volatile("cp.async.commit_group;" ::: "memory")
__device__ __forceinline__ uint32_t swz(uint32_t off) { return off ^ ((off >> 3) & 0x70); }

// vector atomic add (sm_90+): 2 adjacent fp32, addr 8B-aligned
__device__ __forceinline__ void red_add_v2(float* p, float v0, float v1) {
    asm volatile("red.global.add.v2.f32 [%0], {%1, %2};"
                 :: "l"(p), "f"(v0), "f"(v1) : "memory");
}

// =====================================================================
// Pipelined fp16 GEMM core (128x128 tile, K-chunk 64, 3-stage cp.async,
// single barrier/iter, load issued before compute)
// =====================================================================
struct GemmCtx {
    uint32_t smu;
    uint32_t sa_off[4];
    uint32_t ga_off[4];
    int wm, wn, a_r, a_k16, b_r, b_k16, g, c2;
};

__device__ __forceinline__ void gemm_setup(GemmCtx& cx, char* sm, int ldk) {
    const int tid = threadIdx.x, wid = tid >> 5, lane = tid & 31;
    cx.smu = s2u(sm);
    cx.wm = wid >> 1; cx.wn = wid & 1;
    cx.a_r = lane & 15;          cx.a_k16 = (lane >> 4) * 16;
    cx.b_r = ((lane >> 4) << 3) + (lane & 7);
    cx.b_k16 = ((lane >> 3) & 1) * 16;
    cx.g = lane >> 2; cx.c2 = (lane & 3) << 1;
#pragma unroll
    for (int t = 0; t < 4; t++) {
        int idx = tid + t * 256;
        int row = idx >> 3, c16 = idx & 7;
        cx.sa_off[t] = swz((uint32_t)(row * 128 + c16 * 16));
        cx.ga_off[t] = (uint32_t)(row * ldk + c16 * 8);
    }
}

__device__ __forceinline__ void gemm_load(const GemmCtx& cx, int s,
                                          const __half* ag, const __half* bg, int ks) {
#pragma unroll
    for (int t = 0; t < 4; t++)
        cpa16(cx.smu + s * STG + cx.sa_off[t], ag + cx.ga_off[t] + ks);
#pragma unroll
    for (int t = 0; t < 4; t++)
        cpa16(cx.smu + s * STG + TB + cx.sa_off[t], bg + cx.ga_off[t] + ks);
    CPA_COMMIT();
}

__device__ __forceinline__ void gemm_compute(const GemmCtx& cx, int s, float acc[2][8][4]) {
    const uint32_t sbase = cx.smu + s * STG;
#pragma unroll
    for (int kt = 0; kt < 4; kt++) {
        unsigned a[2][4], b[8][2];
#pragma unroll
        for (int mt = 0; mt < 2; mt++) {
            uint32_t off = (uint32_t)((cx.wm * 32 + mt * 16 + cx.a_r) * 128 + kt * 32 + cx.a_k16);
            ldsm_x4(a[mt][0], a[mt][1], a[mt][2], a[mt][3], sbase + swz(off));
        }
#pragma unroll
        for (int np = 0; np < 4; np++) {
            uint32_t off = (uint32_t)((cx.wn * 64 + np * 16 + cx.b_r) * 128 + kt * 32 + cx.b_k16);
            unsigned r0, r1, r2, r3;
            ldsm_x4(r0, r1, r2, r3, sbase + TB + swz(off));
            b[np * 2][0] = r0; b[np * 2][1] = r1;
            b[np * 2 + 1][0] = r2; b[np * 2 + 1][1] = r3;
        }
#pragma unroll
        for (int mt = 0; mt < 2; mt++)
#pragma unroll
            for (int nt = 0; nt < 8; nt++)
                mma_f16(acc[mt][nt], a[mt], b[nt]);
    }
}

#define GEMM_MAINLOOP(NIT, AG, BG)                                          \
    gemm_load(cx, 0, AG, BG, 0);                                            \
    gemm_load(cx, 1, AG, BG, KCH);                                          \
    for (int it = 0; it < (NIT); it++) {                                    \
        if (it + 2 < (NIT)) asm volatile("cp.async.wait_group 1;" ::: "memory"); \
        else                asm volatile("cp.async.wait_group 0;" ::: "memory"); \
        __syncthreads();                                                    \
        if (it + 2 < (NIT)) gemm_load(cx, (it + 2) % 3, AG, BG, (it + 2) * KCH); \
        gemm_compute(cx, it % 3, acc);                                      \
    }

// ---------------- GEMM1: h = silu(g_ax @ w1h[e]^T + b1[e]);
//                  guaranteed-idle blocks (rt>=32) convert w2 -> fp16 ----------------
__global__ void __launch_bounds__(256, 2) gemm1_kernel(const float* __restrict__ b1,
                                                       const float* __restrict__ w2,
                                                       __half* __restrict__ w2h) {
    const int e   = blockIdx.z;
    const int rt  = blockIdx.x;
    const int ct  = blockIdx.y;
    const int tid = threadIdx.x;

    if (rt >= 32) {
        // counts <= 4096 => rt*128 >= 4096 blocks never have compute work.
        // Each converts one static 4096-element stripe of w2.
        const int widx = (e * 16 + ct) * 32 + (rt - 32);   // [0, 4096)
        const int j0 = widx * W2_SE;
#pragma unroll
        for (int i = 0; i < W2_SE / (256 * 4); i++) {
            int j = j0 + (i * 256 + tid) * 4;
            float4 v = *reinterpret_cast<const float4*>(w2 + j);
            *reinterpret_cast<__half2*>(w2h + j)     = __float22half2_rn(make_float2(v.x, v.y));
            *reinterpret_cast<__half2*>(w2h + j + 2) = __float22half2_rn(make_float2(v.z, v.w));
        }
        return;
    }

    const int cnt = g_counts[e];
    if (rt * 128 >= cnt) return;
    const int base = g_aoff[e];

    extern __shared__ __align__(1024) char sm[];
    GemmCtx cx;
    gemm_setup(cx, sm, DM);

    const __half* ag = g_ax  + (size_t)(base + rt * 128) * DM;
    const __half* bg = g_w1h + ((size_t)e * FFH + (size_t)ct * 128) * DM;

    float acc[2][8][4];
#pragma unroll
    for (int mt = 0; mt < 2; mt++)
#pragma unroll
        for (int nt = 0; nt < 8; nt++)
#pragma unroll
            for (int q = 0; q < 4; q++) acc[mt][nt][q] = 0.0f;

    GEMM_MAINLOOP(DM / KCH, ag, bg);

#pragma unroll
    for (int mt = 0; mt < 2; mt++) {
#pragma unroll
        for (int hf = 0; hf < 2; hf++) {
            int r = rt * 128 + cx.wm * 32 + mt * 16 + hf * 8 + cx.g;
            if (r >= cnt) continue;
            size_t hrow = (size_t)(base + r) * FFH;
#pragma unroll
            for (int nt = 0; nt < 8; nt++) {
                int col = ct * 128 + cx.wn * 64 + nt * 8 + cx.c2;
                float v0 = acc[mt][nt][hf * 2 + 0] + b1[e * FFH + col];
                float v1 = acc[mt][nt][hf * 2 + 1] + b1[e * FFH + col + 1];
                float s0 = __fdividef(v0, 1.0f + __expf(-v0));
                float s1 = __fdividef(v1, 1.0f + __expf(-v1));
                *reinterpret_cast<__half2*>(&g_hbuf[hrow + col]) =
                    __float22half2_rn(make_float2(s0, s1));
            }
        }
    }
}

// ---------------- GEMM2: out += cw * (hbuf @ w2h[e]^T + b2[e]) ----------------
__global__ void __launch_bounds__(256, 2) gemm2_kernel(const float* __restrict__ b2,
                                                       float* __restrict__ out) {
    const int e   = blockIdx.z;
    const int cnt = g_counts[e];
    const int rt  = blockIdx.x;
    if (rt * 128 >= cnt) return;
    const int base = g_aoff[e];
    const int ct   = blockIdx.y;

    extern __shared__ __align__(1024) char sm[];
    GemmCtx cx;
    gemm_setup(cx, sm, FFH);

    const __half* ag = g_hbuf + (size_t)(base + rt * 128) * FFH;
    const __half* bg = g_w2h  + ((size_t)e * DM + (size_t)ct * 128) * FFH;

    float acc[2][8][4];
#pragma unroll
    for (int mt = 0; mt < 2; mt++)
#pragma unroll
        for (int nt = 0; nt < 8; nt++)
#pragma unroll
            for (int q = 0; q < 4; q++) acc[mt][nt][q] = 0.0f;

    GEMM_MAINLOOP(FFH / KCH, ag, bg);

#pragma unroll
    for (int mt = 0; mt < 2; mt++) {
#pragma unroll
        for (int hf = 0; hf < 2; hf++) {
            int r = rt * 128 + cx.wm * 32 + mt * 16 + hf * 8 + cx.g;
            if (r >= cnt) continue;
            int tok  = g_slot[base + r];
            float cw = g_slotw[base + r];
            float* orow = out + (size_t)tok * DM;
#pragma unroll
            for (int nt = 0; nt < 8; nt++) {
                int col = ct * 128 + cx.wn * 64 + nt * 8 + cx.c2;
                float v0 = acc[mt][nt][hf * 2 + 0] + b2[e * DM + col];
                float v1 = acc[mt][nt][hf * 2 + 1] + b2[e * DM + col + 1];
                red_add_v2(orow + col, cw * v0, cw * v1);
            }
        }
    }
}

// ---------------- launch ----------------
extern "C" void kernel_launch(void* const* d_in, const int* in_sizes, int n_in,
                              void* d_out, int out_size) {
    const float* x  = (const float*)d_in[0];
    const float* rw = (const float*)d_in[1];
    const float* w1 = (const float*)d_in[2];
    const float* b1 = (const float*)d_in[3];
    const float* w2 = (const float*)d_in[4];
    const float* b2 = (const float*)d_in[5];
    float* out = (float*)d_out;

    float* auxp = (out_size > N_TOK * DM) ? (out + (size_t)N_TOK * DM) : nullptr;

    cudaFuncSetAttribute(gemm1_kernel, cudaFuncAttributeMaxDynamicSharedMemorySize, GSMEM);
    cudaFuncSetAttribute(gemm2_kernel, cudaFuncAttributeMaxDynamicSharedMemorySize, GSMEM);

    __half* w1h; cudaGetSymbolAddress((void**)&w1h, g_w1h);
    __half* w2h; cudaGetSymbolAddress((void**)&w2h, g_w2h);

    init_small<<<1, 32>>>();
    prep_kernel<<<PREP_GRID, 256>>>(x, rw, w1, w1h, out, out_size);
    finalize_kernel<<<1, 32>>>(auxp);
    scatter_kernel<<<(N_TOK + 255) / 256, 256>>>();
    gather_kernel<<<ROWS_PAD / 2, 256>>>(x);

    dim3 g1(64, FFH / 128, N_EXP);   // rt<32: compute; rt>=32: w2 cvt stripes
    gemm1_kernel<<<g1, 256, GSMEM>>>(b1, w2, w2h);

    dim3 g2(32, DM / 128, N_EXP);
    gemm2_kernel<<<g2, 256, GSMEM>>>(b2, out);
}

// round 13
// speedup vs baseline: 1.1136x; 1.0248x over previous
#include <cuda_runtime.h>
#include <cuda_fp16.h>
#include <stdint.h>
#include <math.h>

#define N_TOK   4096
#define DM      1024
#define N_EXP   8
#define FFH     2048
#define CAP     4096                     // fixed rows per expert (top-2 distinct => cnt<=4096)
#define NROWS   (N_EXP * CAP)            // 32768

#define KCH  64                 // halves per K chunk (128 bytes/row)
#define TB   16384              // one 128-row tile: 128*128 bytes
#define STG  (2*TB)             // A+B per stage
#define NSTG 3
#define GSMEM (NSTG*STG)        // 98304 bytes dynamic smem

#define RB   512                // router blocks in prep kernel
#define CB   512                // w1 cvt blocks (w2 cvt rides in gemm1)
#define ZB   128                // zero-out blocks
#define PREP_GRID (RB + CB + ZB)

#define W2_ELEMS (N_EXP * DM * FFH)      // 16.8M
#define W2_SE    (W2_ELEMS / 4096)       // 4096 elements per idle-block stripe

// ---------------- device scratch ----------------
__device__ __half g_hbuf[(size_t)NROWS * FFH];     // fp16 hidden acts (134MB)
__device__ __half g_ax[(size_t)NROWS * DM];        // fp16 gathered x (67MB)
__device__ __half g_w1h[(size_t)N_EXP * FFH * DM]; // fp16 w1
__device__ __half g_w2h[(size_t)N_EXP * DM * FFH]; // fp16 w2
__device__ int   g_slot[NROWS];
__device__ float g_slotw[NROWS];
__device__ int   g_counts[N_EXP];       // via cursor (same value)
__device__ float g_probsum[N_EXP];
__device__ int   g_cursor[N_EXP];

// ---------------- tiny init ----------------
__global__ void init_small() {
    if (threadIdx.x < N_EXP) {
        g_counts[threadIdx.x]  = 0;
        g_cursor[threadIdx.x]  = 0;
        g_probsum[threadIdx.x] = 0.0f;
    }
}

// ---------------- fused prep: router(+scatter+gather) || w1 cvt || zero out ----------------
__global__ void __launch_bounds__(256) prep_kernel(const float* __restrict__ x,
                                                   const float* __restrict__ rw,
                                                   const float* __restrict__ w1,
                                                   __half* __restrict__ w1h,
                                                   float* __restrict__ out,
                                                   int out_elems) {
    const int bb  = blockIdx.x;
    const int tid = threadIdx.x;

    if (bb < RB) {
        // ---------- router: warp per token; full x row lives in registers ----------
        __shared__ float s_ps[N_EXP];
        __shared__ int   s_cnt[N_EXP];
        const int wid  = tid >> 5, lane = tid & 31;
        const int warp = bb * 8 + wid;          // token id (RB*8 == N_TOK)

        if (tid < N_EXP) { s_ps[tid] = 0.0f; s_cnt[tid] = 0; }
        __syncthreads();

        const float4* xr = reinterpret_cast<const float4*>(x + (size_t)warp * DM);
        float4 xv[8];
#pragma unroll
        for (int it = 0; it < 8; it++) xv[it] = xr[lane + it * 32];

        float acc[N_EXP];
#pragma unroll
        for (int e = 0; e < N_EXP; e++) acc[e] = 0.0f;
#pragma unroll
        for (int it = 0; it < 8; it++) {
            const int v4 = lane + it * 32;
#pragma unroll
            for (int e = 0; e < N_EXP; e++) {
                float4 wv = *reinterpret_cast<const float4*>(rw + e * DM + v4 * 4);
                acc[e] += fmaf(xv[it].x, wv.x, fmaf(xv[it].y, wv.y,
                               fmaf(xv[it].z, wv.z, xv[it].w * wv.w)));
            }
        }
#pragma unroll
        for (int e = 0; e < N_EXP; e++) {
#pragma unroll
            for (int o = 16; o > 0; o >>= 1)
                acc[e] += __shfl_xor_sync(0xFFFFFFFFu, acc[e], o);
        }

        int s0 = 0, s1 = 0;
        if (lane == 0) {
            float m = acc[0];
#pragma unroll
            for (int e = 1; e < N_EXP; e++) m = fmaxf(m, acc[e]);
            float ex[N_EXP], s = 0.0f;
#pragma unroll
            for (int e = 0; e < N_EXP; e++) { ex[e] = expf(acc[e] - m); s += ex[e]; }
            float inv = 1.0f / s;

            int i0 = 0;
#pragma unroll
            for (int e = 1; e < N_EXP; e++) if (acc[e] > acc[i0]) i0 = e;
            int i1 = -1;
#pragma unroll
            for (int e = 0; e < N_EXP; e++) {
                if (e == i0) continue;
                if (i1 < 0 || acc[e] > acc[i1]) i1 = e;
            }
            float p0 = ex[i0] * inv, p1 = ex[i1] * inv;
            float rcp = 1.0f / (p0 + p1);

            // claim slots in fixed per-expert regions; write slot metadata
            int c0 = atomicAdd(&g_cursor[i0], 1);
            int c1 = atomicAdd(&g_cursor[i1], 1);
            s0 = i0 * CAP + c0;
            s1 = i1 * CAP + c1;
            g_slot[s0]  = warp; g_slotw[s0] = p0 * rcp;
            g_slot[s1]  = warp; g_slotw[s1] = p1 * rcp;

            atomicAdd(&s_cnt[i0], 1);
            atomicAdd(&s_cnt[i1], 1);
#pragma unroll
            for (int e = 0; e < N_EXP; e++)
                atomicAdd(&s_ps[e], ex[e] * inv);
        }
        s0 = __shfl_sync(0xFFFFFFFFu, s0, 0);
        s1 = __shfl_sync(0xFFFFFFFFu, s1, 0);

        // write the fp16 row (already in registers) to both expert slots
        __half* d0 = g_ax + (size_t)s0 * DM;
        __half* d1 = g_ax + (size_t)s1 * DM;
#pragma unroll
        for (int it = 0; it < 8; it++) {
            const int c = 4 * (lane + it * 32);
            __half2 h0 = __float22half2_rn(make_float2(xv[it].x, xv[it].y));
            __half2 h1 = __float22half2_rn(make_float2(xv[it].z, xv[it].w));
            *reinterpret_cast<__half2*>(d0 + c)     = h0;
            *reinterpret_cast<__half2*>(d0 + c + 2) = h1;
            *reinterpret_cast<__half2*>(d1 + c)     = h0;
            *reinterpret_cast<__half2*>(d1 + c + 2) = h1;
        }

        __syncthreads();
        if (tid < N_EXP) {
            atomicAdd(&g_counts[tid],  s_cnt[tid]);
            atomicAdd(&g_probsum[tid], s_ps[tid]);
        }
    } else if (bb < RB + CB) {
        // ---------- w1 fp32 -> fp16 ----------
        const int cb = bb - RB;
        const int n = N_EXP * FFH * DM;
        const int stride = CB * 256 * 4;
        for (int j = (cb * 256 + tid) * 4; j < n; j += stride) {
            float4 v = *reinterpret_cast<const float4*>(w1 + j);
            *reinterpret_cast<__half2*>(w1h + j)     = __float22half2_rn(make_float2(v.x, v.y));
            *reinterpret_cast<__half2*>(w1h + j + 2) = __float22half2_rn(make_float2(v.z, v.w));
        }
    } else {
        // ---------- zero output ----------
        const int zb = bb - RB - CB;
        const int stride = ZB * 256 * 4;
        const int n4 = out_elems & ~3;
        for (int j = (zb * 256 + tid) * 4; j < n4; j += stride)
            *reinterpret_cast<float4*>(out + j) = make_float4(0.f, 0.f, 0.f, 0.f);
        if (zb == 0 && tid == 0)
            for (int j = n4; j < out_elems; j++) out[j] = 0.0f;
    }
}

// ---------------- finalize: aux loss only ----------------
__global__ void finalize_kernel(float* auxp) {
    if (threadIdx.x == 0 && blockIdx.x == 0 && auxp) {
        float s = 0.0f;
        for (int e = 0; e < N_EXP; e++) {
            float f_i = (float)g_counts[e] / (float)(N_TOK * 2);
            float P_i = g_probsum[e] / (float)N_TOK;
            s += f_i * P_i;
        }
        *auxp = (float)N_EXP * s;
    }
}

// ---------------- mma helpers ----------------
__device__ __forceinline__ uint32_t s2u(const void* p) {
    uint32_t a;
    asm("{ .reg .u64 t; cvta.to.shared.u64 t, %1; cvt.u32.u64 %0, t; }" : "=r"(a) : "l"(p));
    return a;
}
__device__ __forceinline__ void mma_f16(float* c, const unsigned* a, const unsigned* b) {
    asm volatile("mma.sync.aligned.m16n8k16.row.col.f32.f16.f16.f32 "
                 "{%0,%1,%2,%3}, {%4,%5,%6,%7}, {%8,%9}, {%0,%1,%2,%3};"
                 : "+f"(c[0]), "+f"(c[1]), "+f"(c[2]), "+f"(c[3])
                 : "r"(a[0]), "r"(a[1]), "r"(a[2]), "r"(a[3]),
                   "r"(b[0]), "r"(b[1]));
}
__device__ __forceinline__ void ldsm_x4(unsigned& r0, unsigned& r1, unsigned& r2, unsigned& r3,
                                        uint32_t addr) {
    asm volatile("ldmatrix.sync.aligned.m8n8.x4.shared.b16 {%0,%1,%2,%3}, [%4];"
                 : "=r"(r0), "=r"(r1), "=r"(r2), "=r"(r3) : "r"(addr));
}
__device__ __forceinline__ void cpa16(uint32_t saddr, const void* gptr) {
    asm volatile("cp.async.cg.shared.global [%0], [%1], 16;" :: "r"(saddr), "l"(gptr));
}
#define CPA_COMMIT() asm volatile("cp.async.commit_group;" ::: "memory")
__device__ __forceinline__ uint32_t swz(uint32_t off) { return off ^ ((off >> 3) & 0x70); }

// vector atomic add (sm_90+): 2 adjacent fp32, addr 8B-aligned
__device__ __forceinline__ void red_add_v2(float* p, float v0, float v1) {
    asm volatile("red.global.add.v2.f32 [%0], {%1, %2};"
                 :: "l"(p), "f"(v0), "f"(v1) : "memory");
}

// =====================================================================
// Pipelined fp16 GEMM core (128x128 tile, K-chunk 64, 3-stage cp.async,
// single barrier/iter, load issued before compute)
// =====================================================================
struct GemmCtx {
    uint32_t smu;
    uint32_t sa_off[4];
    uint32_t ga_off[4];
    int wm, wn, a_r, a_k16, b_r, b_k16, g, c2;
};

__device__ __forceinline__ void gemm_setup(GemmCtx& cx, char* sm, int ldk) {
    const int tid = threadIdx.x, wid = tid >> 5, lane = tid & 31;
    cx.smu = s2u(sm);
    cx.wm = wid >> 1; cx.wn = wid & 1;
    cx.a_r = lane & 15;          cx.a_k16 = (lane >> 4) * 16;
    cx.b_r = ((lane >> 4) << 3) + (lane & 7);
    cx.b_k16 = ((lane >> 3) & 1) * 16;
    cx.g = lane >> 2; cx.c2 = (lane & 3) << 1;
#pragma unroll
    for (int t = 0; t < 4; t++) {
        int idx = tid + t * 256;
        int row = idx >> 3, c16 = idx & 7;
        cx.sa_off[t] = swz((uint32_t)(row * 128 + c16 * 16));
        cx.ga_off[t] = (uint32_t)(row * ldk + c16 * 8);
    }
}

__device__ __forceinline__ void gemm_load(const GemmCtx& cx, int s,
                                          const __half* ag, const __half* bg, int ks) {
#pragma unroll
    for (int t = 0; t < 4; t++)
        cpa16(cx.smu + s * STG + cx.sa_off[t], ag + cx.ga_off[t] + ks);
#pragma unroll
    for (int t = 0; t < 4; t++)
        cpa16(cx.smu + s * STG + TB + cx.sa_off[t], bg + cx.ga_off[t] + ks);
    CPA_COMMIT();
}

__device__ __forceinline__ void gemm_compute(const GemmCtx& cx, int s, float acc[2][8][4]) {
    const uint32_t sbase = cx.smu + s * STG;
#pragma unroll
    for (int kt = 0; kt < 4; kt++) {
        unsigned a[2][4], b[8][2];
#pragma unroll
        for (int mt = 0; mt < 2; mt++) {
            uint32_t off = (uint32_t)((cx.wm * 32 + mt * 16 + cx.a_r) * 128 + kt * 32 + cx.a_k16);
            ldsm_x4(a[mt][0], a[mt][1], a[mt][2], a[mt][3], sbase + swz(off));
        }
#pragma unroll
        for (int np = 0; np < 4; np++) {
            uint32_t off = (uint32_t)((cx.wn * 64 + np * 16 + cx.b_r) * 128 + kt * 32 + cx.b_k16);
            unsigned r0, r1, r2, r3;
            ldsm_x4(r0, r1, r2, r3, sbase + TB + swz(off));
            b[np * 2][0] = r0; b[np * 2][1] = r1;
            b[np * 2 + 1][0] = r2; b[np * 2 + 1][1] = r3;
        }
#pragma unroll
        for (int mt = 0; mt < 2; mt++)
#pragma unroll
            for (int nt = 0; nt < 8; nt++)
                mma_f16(acc[mt][nt], a[mt], b[nt]);
    }
}

#define GEMM_MAINLOOP(NIT, AG, BG)                                          \
    gemm_load(cx, 0, AG, BG, 0);                                            \
    gemm_load(cx, 1, AG, BG, KCH);                                          \
    for (int it = 0; it < (NIT); it++) {                                    \
        if (it + 2 < (NIT)) asm volatile("cp.async.wait_group 1;" ::: "memory"); \
        else                asm volatile("cp.async.wait_group 0;" ::: "memory"); \
        __syncthreads();                                                    \
        if (it + 2 < (NIT)) gemm_load(cx, (it + 2) % 3, AG, BG, (it + 2) * KCH); \
        gemm_compute(cx, it % 3, acc);                                      \
    }

// ---------------- GEMM1: h = silu(g_ax @ w1h[e]^T + b1[e]);
//                  guaranteed-idle blocks (rt>=32) convert w2 -> fp16 ----------------
__global__ void __launch_bounds__(256, 2) gemm1_kernel(const float* __restrict__ b1,
                                                       const float* __restrict__ w2,
                                                       __half* __restrict__ w2h) {
    const int e   = blockIdx.z;
    const int rt  = blockIdx.x;
    const int ct  = blockIdx.y;
    const int tid = threadIdx.x;

    if (rt >= 32) {
        const int widx = (e * 16 + ct) * 32 + (rt - 32);   // [0, 4096)
        const int j0 = widx * W2_SE;
#pragma unroll
        for (int i = 0; i < W2_SE / (256 * 4); i++) {
            int j = j0 + (i * 256 + tid) * 4;
            float4 v = *reinterpret_cast<const float4*>(w2 + j);
            *reinterpret_cast<__half2*>(w2h + j)     = __float22half2_rn(make_float2(v.x, v.y));
            *reinterpret_cast<__half2*>(w2h + j + 2) = __float22half2_rn(make_float2(v.z, v.w));
        }
        return;
    }

    const int cnt = g_counts[e];
    if (rt * 128 >= cnt) return;
    const int base = e * CAP;

    extern __shared__ __align__(1024) char sm[];
    GemmCtx cx;
    gemm_setup(cx, sm, DM);

    const __half* ag = g_ax  + (size_t)(base + rt * 128) * DM;
    const __half* bg = g_w1h + ((size_t)e * FFH + (size_t)ct * 128) * DM;

    float acc[2][8][4];
#pragma unroll
    for (int mt = 0; mt < 2; mt++)
#pragma unroll
        for (int nt = 0; nt < 8; nt++)
#pragma unroll
            for (int q = 0; q < 4; q++) acc[mt][nt][q] = 0.0f;

    GEMM_MAINLOOP(DM / KCH, ag, bg);

#pragma unroll
    for (int mt = 0; mt < 2; mt++) {
#pragma unroll
        for (int hf = 0; hf < 2; hf++) {
            int r = rt * 128 + cx.wm * 32 + mt * 16 + hf * 8 + cx.g;
            if (r >= cnt) continue;
            size_t hrow = (size_t)(base + r) * FFH;
#pragma unroll
            for (int nt = 0; nt < 8; nt++) {
                int col = ct * 128 + cx.wn * 64 + nt * 8 + cx.c2;
                float v0 = acc[mt][nt][hf * 2 + 0] + b1[e * FFH + col];
                float v1 = acc[mt][nt][hf * 2 + 1] + b1[e * FFH + col + 1];
                float s0 = __fdividef(v0, 1.0f + __expf(-v0));
                float s1 = __fdividef(v1, 1.0f + __expf(-v1));
                *reinterpret_cast<__half2*>(&g_hbuf[hrow + col]) =
                    __float22half2_rn(make_float2(s0, s1));
            }
        }
    }
}

// ---------------- GEMM2: out += cw * (hbuf @ w2h[e]^T + b2[e]) ----------------
__global__ void __launch_bounds__(256, 2) gemm2_kernel(const float* __restrict__ b2,
                                                       float* __restrict__ out) {
    const int e   = blockIdx.z;
    const int cnt = g_counts[e];
    const int rt  = blockIdx.x;
    if (rt * 128 >= cnt) return;
    const int base = e * CAP;
    const int ct   = blockIdx.y;

    extern __shared__ __align__(1024) char sm[];
    GemmCtx cx;
    gemm_setup(cx, sm, FFH);

    const __half* ag = g_hbuf + (size_t)(base + rt * 128) * FFH;
    const __half* bg = g_w2h  + ((size_t)e * DM + (size_t)ct * 128) * FFH;

    float acc[2][8][4];
#pragma unroll
    for (int mt = 0; mt < 2; mt++)
#pragma unroll
        for (int nt = 0; nt < 8; nt++)
#pragma unroll
            for (int q = 0; q < 4; q++) acc[mt][nt][q] = 0.0f;

    GEMM_MAINLOOP(FFH / KCH, ag, bg);

#pragma unroll
    for (int mt = 0; mt < 2; mt++) {
#pragma unroll
        for (int hf = 0; hf < 2; hf++) {
            int r = rt * 128 + cx.wm * 32 + mt * 16 + hf * 8 + cx.g;
            if (r >= cnt) continue;
            int tok  = g_slot[base + r];
            float cw = g_slotw[base + r];
            float* orow = out + (size_t)tok * DM;
#pragma unroll
            for (int nt = 0; nt < 8; nt++) {
                int col = ct * 128 + cx.wn * 64 + nt * 8 + cx.c2;
                float v0 = acc[mt][nt][hf * 2 + 0] + b2[e * DM + col];
                float v1 = acc[mt][nt][hf * 2 + 1] + b2[e * DM + col + 1];
                red_add_v2(orow + col, cw * v0, cw * v1);
            }
        }
    }
}

// ---------------- launch ----------------
extern "C" void kernel_launch(void* const* d_in, const int* in_sizes, int n_in,
                              void* d_out, int out_size) {
    const float* x  = (const float*)d_in[0];
    const float* rw = (const float*)d_in[1];
    const float* w1 = (const float*)d_in[2];
    const float* b1 = (const float*)d_in[3];
    const float* w2 = (const float*)d_in[4];
    const float* b2 = (const float*)d_in[5];
    float* out = (float*)d_out;

    float* auxp = (out_size > N_TOK * DM) ? (out + (size_t)N_TOK * DM) : nullptr;

    cudaFuncSetAttribute(gemm1_kernel, cudaFuncAttributeMaxDynamicSharedMemorySize, GSMEM);
    cudaFuncSetAttribute(gemm2_kernel, cudaFuncAttributeMaxDynamicSharedMemorySize, GSMEM);

    __half* w1h; cudaGetSymbolAddress((void**)&w1h, g_w1h);
    __half* w2h; cudaGetSymbolAddress((void**)&w2h, g_w2h);

    init_small<<<1, 32>>>();
    prep_kernel<<<PREP_GRID, 256>>>(x, rw, w1, w1h, out, out_size);
    finalize_kernel<<<1, 32>>>(auxp);

    dim3 g1(64, FFH / 128, N_EXP);   // rt<32: compute; rt>=32: w2 cvt stripes
    gemm1_kernel<<<g1, 256, GSMEM>>>(b1, w2, w2h);

    dim3 g2(32, DM / 128, N_EXP);
    gemm2_kernel<<<g2, 256, GSMEM>>>(b2, out);
}